// round 12
// baseline (speedup 1.0000x reference)
#include <cuda_runtime.h>
#include <cstdint>

#define D    64
#define BM   128
#define BN   128
#define PAD  68          // words; 68 mod 32 == 4 -> conflict-free fragment LDS
#define NROWS 8192

__device__ float g_sq1[NROWS];
__device__ float g_sq2[NROWS];

// ---------------------------------------------------------------------------
__device__ __forceinline__ uint32_t f2tf32(float f) {
    uint32_t u;
    asm("cvt.rna.tf32.f32 %0, %1;" : "=r"(u) : "f"(f));
    return u;
}
__device__ __forceinline__ float tf32val(float f) {
    return __uint_as_float(f2tf32(f));
}

// ---------------------------------------------------------------------------
// Warp-per-row norms of both inputs (tf32-rounded, self-consistent with MMA).
// 16384 rows -> 2048 CTAs of 8 warps. ~2us.
// ---------------------------------------------------------------------------
__global__ void norm_kernel(const float* __restrict__ x1,
                            const float* __restrict__ x2) {
    const int w = (blockIdx.x * blockDim.x + threadIdx.x) >> 5;
    const int lane = threadIdx.x & 31;
    const float* x = (w < NROWS) ? x1 : x2;
    const int row = w & (NROWS - 1);
    float2 v = *(const float2*)(x + (size_t)row * D + lane * 2);
    float a = tf32val(v.x), b = tf32val(v.y);
    float s = fmaf(a, a, b * b);
#pragma unroll
    for (int o = 16; o; o >>= 1)
        s += __shfl_xor_sync(0xFFFFFFFF, s, o);
    if (lane == 0) {
        if (w < NROWS) g_sq1[row] = s; else g_sq2[row] = s;
    }
}

// ---------------------------------------------------------------------------
// 128x128 tile per CTA, 8 warps (2x4), warp tile 64x32, 2 CTAs/SM (R6 core).
// Epilogue: per-warp 64x32 smem transpose, block-rotation swizzle
// pos = 8*((nf+g)&3) + 2q  (STS.64 conflict-free per half-warp phase,
// LDS.128 readback 16B-aligned and conflict-free), then dense STG.128.
// ---------------------------------------------------------------------------
__global__ __launch_bounds__(256, 2)
void dist_kernel(const float* __restrict__ x1, const float* __restrict__ x2,
                 float* __restrict__ out, int M) {
    extern __shared__ uint32_t smem[];
    uint32_t* sa = smem;                      // [BM][PAD] tf32 bits
    uint32_t* sb = smem + BM * PAD;           // [BN][PAD]
    float* snA = (float*)(smem + 2 * BM * PAD);   // [128] A row norms
    float* snB = snA + BM;                         // [128] B row norms

    const int n0  = blockIdx.y * BM;
    const int m0  = blockIdx.x * BN;
    const int tid = threadIdx.x;
    const int wid = tid >> 5;
    const int lane = tid & 31;
    const int wm = wid >> 2;          // 0..1 : 64-row band
    const int wn = wid & 3;           // 0..3 : 32-col band
    const int g  = lane >> 2;         // 0..7
    const int q  = lane & 3;          // 0..3

    // ---- stage tiles: gmem float4 -> tf32(RNA) -> smem; norms -> smem ----
    {
        const int c4 = (tid & 15) * 4;
        const int rb = tid >> 4;
#pragma unroll
        for (int p = 0; p < 8; ++p) {
            int r = rb + p * 16;
            float4 va = *(const float4*)(x1 + (size_t)(n0 + r) * D + c4);
            float4 vb = *(const float4*)(x2 + (size_t)(m0 + r) * D + c4);
            *(uint4*)(sa + r * PAD + c4) =
                make_uint4(f2tf32(va.x), f2tf32(va.y), f2tf32(va.z), f2tf32(va.w));
            *(uint4*)(sb + r * PAD + c4) =
                make_uint4(f2tf32(vb.x), f2tf32(vb.y), f2tf32(vb.z), f2tf32(vb.w));
        }
        if (tid < BM) snA[tid] = g_sq1[n0 + tid];
        else          snB[tid - BM] = g_sq2[m0 + tid - BM];
    }
    __syncthreads();

    float acc[4][4][4];
#pragma unroll
    for (int i = 0; i < 4; ++i)
#pragma unroll
        for (int j = 0; j < 4; ++j)
#pragma unroll
            for (int c = 0; c < 4; ++c) acc[i][j][c] = 0.f;

    // ---- K loop: 8 steps of k=8 (validated R6 core) ----
#pragma unroll
    for (int ks = 0; ks < 8; ++ks) {
        const int kb = ks * 8;
        uint32_t bfr[4][2];
#pragma unroll
        for (int nf = 0; nf < 4; ++nf) {
            const uint32_t* bp = sb + (wn * 32 + nf * 8 + g) * PAD + kb + q;
            bfr[nf][0] = bp[0];
            bfr[nf][1] = bp[4];
        }
#pragma unroll
        for (int mf = 0; mf < 4; ++mf) {
            const int r = wm * 64 + mf * 16 + g;
            const uint32_t* ap = sa + r * PAD + kb + q;
            uint32_t a0 = ap[0];
            uint32_t a1 = ap[8 * PAD];
            uint32_t a2 = ap[4];
            uint32_t a3 = ap[8 * PAD + 4];
#pragma unroll
            for (int nf = 0; nf < 4; ++nf) {
                asm volatile(
                    "mma.sync.aligned.m16n8k8.row.col.f32.tf32.tf32.f32 "
                    "{%0,%1,%2,%3}, {%4,%5,%6,%7}, {%8,%9}, {%0,%1,%2,%3};"
                    : "+f"(acc[mf][nf][0]), "+f"(acc[mf][nf][1]),
                      "+f"(acc[mf][nf][2]), "+f"(acc[mf][nf][3])
                    : "r"(a0), "r"(a1), "r"(a2), "r"(a3),
                      "r"(bfr[nf][0]), "r"(bfr[nf][1]));
            }
        }
    }

    // ---- read norms to registers BEFORE smem reuse ----
    float s1lo[4], s1hi[4];
#pragma unroll
    for (int mf = 0; mf < 4; ++mf) {
        s1lo[mf] = snA[wm * 64 + mf * 16 + g];
        s1hi[mf] = snA[wm * 64 + mf * 16 + g + 8];
    }
    float2 s2v[4];
#pragma unroll
    for (int nf = 0; nf < 4; ++nf)
        s2v[nf] = *(const float2*)&snB[wn * 32 + nf * 8 + 2 * q];

    __syncthreads();   // fragment + norm reads done; sa/sb become warp buffers

    // ---- phase 1: d2 -> per-warp 64x32 swizzled buffer ----
    float* buf = (float*)smem + wid * 2048;    // 64 rows x 32 cols
#pragma unroll
    for (int mf = 0; mf < 4; ++mf) {
        const int rl0 = mf * 16 + g;
#pragma unroll
        for (int nf = 0; nf < 4; ++nf) {
            const int cl = 8 * ((nf + g) & 3) + 2 * q;   // swizzled position
            float2 ra, rb;
            ra.x = fmaxf(fmaf(-2.f, acc[mf][nf][0], s1lo[mf] + s2v[nf].x), 0.f);
            ra.y = fmaxf(fmaf(-2.f, acc[mf][nf][1], s1lo[mf] + s2v[nf].y), 0.f);
            rb.x = fmaxf(fmaf(-2.f, acc[mf][nf][2], s1hi[mf] + s2v[nf].x), 0.f);
            rb.y = fmaxf(fmaf(-2.f, acc[mf][nf][3], s1hi[mf] + s2v[nf].y), 0.f);
            *(float2*)(buf + rl0 * 32 + cl)       = ra;
            *(float2*)(buf + (rl0 + 8) * 32 + cl) = rb;   // (rl0+8)&7 == g
        }
    }
    __syncwarp();

    // ---- phase 2: de-swizzled readback -> STG.128 (4 dense lines/instr) ----
    {
        const int rh = lane >> 3;            // 0..3 : row within quad
        const int j  = lane & 7;             // float4 index within 32-col row
#pragma unroll
        for (int t = 0; t < 16; ++t) {
            const int rl = t * 4 + rh;       // local row 0..63
            const int w  = rl * 32 + 8 * (((j >> 1) + (rl & 7)) & 3) + 4 * (j & 1);
            const float4 v = *(const float4*)(buf + w);
            __stcs((float4*)(out + (size_t)(n0 + wm * 64 + rl) * M
                                  + m0 + wn * 32 + 4 * j), v);
        }
    }
}

// ---------------------------------------------------------------------------
extern "C" void kernel_launch(void* const* d_in, const int* in_sizes, int n_in,
                              void* d_out, int out_size) {
    const float* x1 = (const float*)d_in[0];
    const float* x2 = (const float*)d_in[1];
    float* out = (float*)d_out;

    const int N = in_sizes[0] / D;   // 8192
    const int M = in_sizes[1] / D;   // 8192

    const int smem_bytes = 2 * BM * PAD * sizeof(uint32_t)
                         + 2 * BM * sizeof(float);   // 70656
    cudaFuncSetAttribute(dist_kernel,
                         cudaFuncAttributeMaxDynamicSharedMemorySize, smem_bytes);

    norm_kernel<<<2 * NROWS * 32 / 256, 256>>>(x1, x2);

    dim3 grid(M / BN, N / BM);
    dist_kernel<<<grid, 256, smem_bytes>>>(x1, x2, out, M);
}

// round 13
// speedup vs baseline: 1.1427x; 1.1427x over previous
#include <cuda_runtime.h>
#include <cstdint>

#define D    64
#define BM   128
#define BN   128
#define PAD  72          // words; 72 mod 32 == 8 -> conflict-free LDS.64 fragment phases
#define NROWS 8192

__device__ float g_sq1[NROWS];
__device__ float g_sq2[NROWS];

// ---------------------------------------------------------------------------
__device__ __forceinline__ uint32_t f2tf32(float f) {
    uint32_t u;
    asm("cvt.rna.tf32.f32 %0, %1;" : "=r"(u) : "f"(f));
    return u;
}
__device__ __forceinline__ float tf32val(float f) {
    return __uint_as_float(f2tf32(f));
}

// ---------------------------------------------------------------------------
// Warp-per-row norms of both inputs (tf32-rounded, self-consistent with MMA).
// ---------------------------------------------------------------------------
__global__ void norm_kernel(const float* __restrict__ x1,
                            const float* __restrict__ x2) {
    const int w = (blockIdx.x * blockDim.x + threadIdx.x) >> 5;
    const int lane = threadIdx.x & 31;
    const float* x = (w < NROWS) ? x1 : x2;
    const int row = w & (NROWS - 1);
    float2 v = *(const float2*)(x + (size_t)row * D + lane * 2);
    float a = tf32val(v.x), b = tf32val(v.y);
    float s = fmaf(a, a, b * b);
#pragma unroll
    for (int o = 16; o; o >>= 1)
        s += __shfl_xor_sync(0xFFFFFFFF, s, o);
    if (lane == 0) {
        if (w < NROWS) g_sq1[row] = s; else g_sq2[row] = s;
    }
}

// ---------------------------------------------------------------------------
// 128x128 tile per CTA, 8 warps (2x4), warp tile 64x32, 2 CTAs/SM.
// Smem K-interleave: 8-col block b stored at word base(b) = 8b + 4*(b>>2) in
// order [k0,k4,k1,k5,k2,k6,k3,k7] -> each (k=q, k=q+4) fragment pair is one
// LDS.64. Mainloop: 12 LDS.64 + 16 HMMA per k-step (was 24 LDS.32 + 16 HMMA).
// ---------------------------------------------------------------------------
__global__ __launch_bounds__(256, 2)
void dist_kernel(const float* __restrict__ x1, const float* __restrict__ x2,
                 float* __restrict__ out, int M) {
    extern __shared__ uint32_t smem[];
    uint32_t* sa = smem;              // [BM][PAD] interleaved tf32 bits
    uint32_t* sb = smem + BM * PAD;   // [BN][PAD]

    const int n0  = blockIdx.y * BM;
    const int m0  = blockIdx.x * BN;
    const int tid = threadIdx.x;
    const int wid = tid >> 5;
    const int lane = tid & 31;
    const int wm = wid >> 2;          // 0..1 : 64-row band
    const int wn = wid & 3;           // 0..3 : 32-col band
    const int g  = lane >> 2;         // 0..7
    const int q  = lane & 3;          // 0..3

    // ---- stage tiles: 2x LDG.128 per (row, 8-col block), K-interleaved STS ----
#pragma unroll
    for (int it = 0; it < 4; ++it) {
        int idx = tid + it * 256;              // 0..1023 (row, block) pairs
        int r = idx >> 3, b = idx & 7;
        const float4* pa = (const float4*)(x1 + (size_t)(n0 + r) * D + b * 8);
        const float4* pb = (const float4*)(x2 + (size_t)(m0 + r) * D + b * 8);
        float4 a0 = pa[0], a1 = pa[1];
        float4 b0 = pb[0], b1 = pb[1];
        int base = r * PAD + b * 8 + 4 * (b >> 2);
        *(uint4*)(sa + base) =
            make_uint4(f2tf32(a0.x), f2tf32(a1.x), f2tf32(a0.y), f2tf32(a1.y));
        *(uint4*)(sa + base + 4) =
            make_uint4(f2tf32(a0.z), f2tf32(a1.z), f2tf32(a0.w), f2tf32(a1.w));
        *(uint4*)(sb + base) =
            make_uint4(f2tf32(b0.x), f2tf32(b1.x), f2tf32(b0.y), f2tf32(b1.y));
        *(uint4*)(sb + base + 4) =
            make_uint4(f2tf32(b0.z), f2tf32(b1.z), f2tf32(b0.w), f2tf32(b1.w));
    }
    __syncthreads();

    float acc[4][4][4];
#pragma unroll
    for (int i = 0; i < 4; ++i)
#pragma unroll
        for (int j = 0; j < 4; ++j)
#pragma unroll
            for (int c = 0; c < 4; ++c) acc[i][j][c] = 0.f;

    // ---- K loop: 8 steps of k=8, paired LDS.64 fragment loads ----
#pragma unroll
    for (int ks = 0; ks < 8; ++ks) {
        const int kbase = 8 * ks + 4 * (ks >> 2) + 2 * q;

        uint2 bfr[4];                 // .x = k(q), .y = k(q+4)
#pragma unroll
        for (int nf = 0; nf < 4; ++nf)
            bfr[nf] = *(const uint2*)(sb + (wn * 32 + nf * 8 + g) * PAD + kbase);

#pragma unroll
        for (int mf = 0; mf < 4; ++mf) {
            const int r = wm * 64 + mf * 16 + g;
            uint2 alo = *(const uint2*)(sa + r * PAD + kbase);        // a0, a2
            uint2 ahi = *(const uint2*)(sa + (r + 8) * PAD + kbase);  // a1, a3
#pragma unroll
            for (int nf = 0; nf < 4; ++nf) {
                asm volatile(
                    "mma.sync.aligned.m16n8k8.row.col.f32.tf32.tf32.f32 "
                    "{%0,%1,%2,%3}, {%4,%5,%6,%7}, {%8,%9}, {%0,%1,%2,%3};"
                    : "+f"(acc[mf][nf][0]), "+f"(acc[mf][nf][1]),
                      "+f"(acc[mf][nf][2]), "+f"(acc[mf][nf][3])
                    : "r"(alo.x), "r"(ahi.x), "r"(alo.y), "r"(ahi.y),
                      "r"(bfr[nf].x), "r"(bfr[nf].y));
            }
        }
    }

    // ---- epilogue: d2 = max(s1 + s2 - 2*cross, 0), streaming stores ----
#pragma unroll
    for (int mf = 0; mf < 4; ++mf) {
        const int r_lo = n0 + wm * 64 + mf * 16 + g;
        const float s1a = __ldg(&g_sq1[r_lo]);
        const float s1b = __ldg(&g_sq1[r_lo + 8]);
        float* orow_a = out + (size_t)r_lo * M + m0;
        float* orow_b = orow_a + (size_t)8 * M;
#pragma unroll
        for (int nf = 0; nf < 4; ++nf) {
            const int cidx = wn * 32 + nf * 8 + q * 2;
            const float2 s2 = __ldg((const float2*)&g_sq2[m0 + cidx]);
            float2 ra, rb;
            ra.x = fmaxf(fmaf(-2.f, acc[mf][nf][0], s1a + s2.x), 0.f);
            ra.y = fmaxf(fmaf(-2.f, acc[mf][nf][1], s1a + s2.y), 0.f);
            rb.x = fmaxf(fmaf(-2.f, acc[mf][nf][2], s1b + s2.x), 0.f);
            rb.y = fmaxf(fmaf(-2.f, acc[mf][nf][3], s1b + s2.y), 0.f);
            __stcs((float2*)(orow_a + cidx), ra);
            __stcs((float2*)(orow_b + cidx), rb);
        }
    }
}

// ---------------------------------------------------------------------------
extern "C" void kernel_launch(void* const* d_in, const int* in_sizes, int n_in,
                              void* d_out, int out_size) {
    const float* x1 = (const float*)d_in[0];
    const float* x2 = (const float*)d_in[1];
    float* out = (float*)d_out;

    const int N = in_sizes[0] / D;   // 8192
    const int M = in_sizes[1] / D;   // 8192

    const int smem_bytes = 2 * BM * PAD * sizeof(uint32_t);  // 73728
    cudaFuncSetAttribute(dist_kernel,
                         cudaFuncAttributeMaxDynamicSharedMemorySize, smem_bytes);

    norm_kernel<<<2 * NROWS * 32 / 256, 256>>>(x1, x2);

    dim3 grid(M / BN, N / BM);
    dist_kernel<<<grid, 256, smem_bytes>>>(x1, x2, out, M);
}